// round 1
// baseline (speedup 1.0000x reference)
#include <cuda_runtime.h>

// CapsuleLayer dynamic routing, fully fused.
// x: [B=256, N=1152, CI=8] f32   (d_in[0])
// w: [C=10, N=1152, CI=8, CO=16] f32 (d_in[1])
// out: [C, B, 1, 1, CO=16] f32
//
// One CTA handles (c, pair of b). Priors for the pair live in SMEM (padded
// rows of 17 floats -> conflict-free row AND column access). All 3 routing
// iterations run out of SMEM; only 32 floats written to HBM per CTA.

#define Cc   10
#define Bb   256
#define Nn   1152
#define CIi  8
#define COo  16
#define Gg   2
#define NPAD 17
#define NTHREADS 512
#define RGROUP   256   // threads per b-group

// smem layout (floats):
//   P      : Gg*Nn*NPAD = 39168
//   logits : Gg*Nn      = 2304
//   evals  : Gg*Nn      = 2304
//   wred   : Gg*8*16    = 256
//   sred   : Gg*8       = 16
//   outv   : Gg*16      = 32
#define SMEM_FLOATS (Gg*Nn*NPAD + Gg*Nn + Gg*Nn + Gg*8*16 + Gg*8 + Gg*16)
#define SMEM_BYTES  (SMEM_FLOATS * 4)

__global__ __launch_bounds__(NTHREADS, 1)
void capsule_routing_kernel(const float* __restrict__ x,
                            const float* __restrict__ w,
                            float* __restrict__ out)
{
    extern __shared__ float sm[];
    float* P      = sm;
    float* logits = P + Gg*Nn*NPAD;
    float* evals  = logits + Gg*Nn;
    float* wred   = evals + Gg*Nn;
    float* sred   = wred + Gg*8*16;
    float* outv   = sred + Gg*8;

    const int tid  = threadIdx.x;
    const int c    = blockIdx.x / (Bb/Gg);
    const int b0   = (blockIdx.x % (Bb/Gg)) * Gg;

    // ---------------- Phase 1: priors into SMEM ----------------
    // task -> (g = task&1, n = task>>1): lane pairs share n so w loads dedup.
    for (int task = tid; task < Gg*Nn; task += NTHREADS) {
        const int g = task & 1;
        const int n = task >> 1;
        const float* xp = x + ((b0 + g)*Nn + n)*CIi;
        float4 xa = *(const float4*)(xp);
        float4 xb = *(const float4*)(xp + 4);
        float xi[8] = {xa.x, xa.y, xa.z, xa.w, xb.x, xb.y, xb.z, xb.w};

        const float* wp = w + ((c*Nn + n)*CIi)*COo;
        float acc[16];
        #pragma unroll
        for (int o = 0; o < 16; ++o) acc[o] = 0.f;

        #pragma unroll
        for (int i = 0; i < 8; ++i) {
            const float xv = xi[i];
            float4 w0 = *(const float4*)(wp + i*16 + 0);
            float4 w1 = *(const float4*)(wp + i*16 + 4);
            float4 w2 = *(const float4*)(wp + i*16 + 8);
            float4 w3 = *(const float4*)(wp + i*16 + 12);
            acc[0]  = fmaf(xv, w0.x, acc[0]);
            acc[1]  = fmaf(xv, w0.y, acc[1]);
            acc[2]  = fmaf(xv, w0.z, acc[2]);
            acc[3]  = fmaf(xv, w0.w, acc[3]);
            acc[4]  = fmaf(xv, w1.x, acc[4]);
            acc[5]  = fmaf(xv, w1.y, acc[5]);
            acc[6]  = fmaf(xv, w1.z, acc[6]);
            acc[7]  = fmaf(xv, w1.w, acc[7]);
            acc[8]  = fmaf(xv, w2.x, acc[8]);
            acc[9]  = fmaf(xv, w2.y, acc[9]);
            acc[10] = fmaf(xv, w2.z, acc[10]);
            acc[11] = fmaf(xv, w2.w, acc[11]);
            acc[12] = fmaf(xv, w3.x, acc[12]);
            acc[13] = fmaf(xv, w3.y, acc[13]);
            acc[14] = fmaf(xv, w3.z, acc[14]);
            acc[15] = fmaf(xv, w3.w, acc[15]);
        }
        float* pr = P + (g*Nn + n)*NPAD;
        #pragma unroll
        for (int o = 0; o < 16; ++o) pr[o] = acc[o];
    }
    __syncthreads();

    // ---------------- Phase 2: routing iterations ----------------
    const int g    = tid / RGROUP;       // which b in the pair
    const int r    = tid % RGROUP;
    const int lane = r & 31;
    const int wg   = r >> 5;             // warp within group, 0..7
    float* Pg = P + g*Nn*NPAD;
    float* Lg = logits + g*Nn;
    float* Eg = evals  + g*Nn;

    // --- iteration 0: uniform probs -> s = mean_n priors ---
    {
        float acc[16];
        #pragma unroll
        for (int o = 0; o < 16; ++o) acc[o] = 0.f;
        for (int n = r; n < Nn; n += RGROUP) {
            const float* pr = Pg + n*NPAD;
            #pragma unroll
            for (int o = 0; o < 16; ++o) acc[o] += pr[o];
        }
        #pragma unroll
        for (int off = 16; off >= 1; off >>= 1)
            #pragma unroll
            for (int o = 0; o < 16; ++o)
                acc[o] += __shfl_xor_sync(0xffffffffu, acc[o], off);
        if (lane == 0) {
            #pragma unroll
            for (int o = 0; o < 16; ++o) wred[(g*8 + wg)*16 + o] = acc[o];
        }
        __syncthreads();
        if (wg == 0) {
            float sv = 0.f;
            if (lane < 16) {
                #pragma unroll
                for (int wi = 0; wi < 8; ++wi) sv += wred[(g*8 + wi)*16 + lane];
                sv *= (1.0f / Nn);
            }
            float sq = (lane < 16) ? sv*sv : 0.f;
            #pragma unroll
            for (int off = 16; off >= 1; off >>= 1)
                sq += __shfl_xor_sync(0xffffffffu, sq, off);
            const float coef = sq / (1.f + sq) * rsqrtf(sq);
            if (lane < 16) outv[g*16 + lane] = sv * coef;
        }
        __syncthreads();
    }

    // --- iterations 1 and 2 ---
    for (int it = 1; it < 3; ++it) {
        float ovr[16];
        #pragma unroll
        for (int o = 0; o < 16; ++o) ovr[o] = outv[g*16 + o];

        // logits update + local max
        float lmax = -1e30f;
        for (int n = r; n < Nn; n += RGROUP) {
            const float* pr = Pg + n*NPAD;
            float dot = 0.f;
            #pragma unroll
            for (int o = 0; o < 16; ++o) dot = fmaf(pr[o], ovr[o], dot);
            const float L = (it == 1) ? dot : (Lg[n] + dot);
            Lg[n] = L;
            lmax  = fmaxf(lmax, L);
        }
        #pragma unroll
        for (int off = 16; off >= 1; off >>= 1)
            lmax = fmaxf(lmax, __shfl_xor_sync(0xffffffffu, lmax, off));
        if (lane == 0) sred[g*8 + wg] = lmax;
        __syncthreads();
        float M = -1e30f;
        #pragma unroll
        for (int wi = 0; wi < 8; ++wi) M = fmaxf(M, sred[g*8 + wi]);

        // exp + local Z  (each thread touches only its own n's)
        float lsum = 0.f;
        for (int n = r; n < Nn; n += RGROUP) {
            const float ev = __expf(Lg[n] - M);
            Eg[n] = ev;
            lsum += ev;
        }
        #pragma unroll
        for (int off = 16; off >= 1; off >>= 1)
            lsum += __shfl_xor_sync(0xffffffffu, lsum, off);
        __syncthreads();                    // all M reads done before sred reuse
        if (lane == 0) sred[g*8 + wg] = lsum;
        __syncthreads();
        float Z = 0.f;
        #pragma unroll
        for (int wi = 0; wi < 8; ++wi) Z += sred[g*8 + wi];

        // weighted column sum: s[o] = (1/Z) * sum_n e[n] * P[n][o]
        float acc[16];
        #pragma unroll
        for (int o = 0; o < 16; ++o) acc[o] = 0.f;
        for (int n = r; n < Nn; n += RGROUP) {
            const float ev = Eg[n];
            const float* pr = Pg + n*NPAD;
            #pragma unroll
            for (int o = 0; o < 16; ++o) acc[o] = fmaf(ev, pr[o], acc[o]);
        }
        #pragma unroll
        for (int off = 16; off >= 1; off >>= 1)
            #pragma unroll
            for (int o = 0; o < 16; ++o)
                acc[o] += __shfl_xor_sync(0xffffffffu, acc[o], off);
        if (lane == 0) {
            #pragma unroll
            for (int o = 0; o < 16; ++o) wred[(g*8 + wg)*16 + o] = acc[o];
        }
        __syncthreads();
        if (wg == 0) {
            float sv = 0.f;
            if (lane < 16) {
                #pragma unroll
                for (int wi = 0; wi < 8; ++wi) sv += wred[(g*8 + wi)*16 + lane];
                sv /= Z;
            }
            float sq = (lane < 16) ? sv*sv : 0.f;
            #pragma unroll
            for (int off = 16; off >= 1; off >>= 1)
                sq += __shfl_xor_sync(0xffffffffu, sq, off);
            const float coef = sq / (1.f + sq) * rsqrtf(sq);
            if (lane < 16) outv[g*16 + lane] = sv * coef;
        }
        __syncthreads();
    }

    // ---------------- write output: [C, B, 1, 1, 16] ----------------
    if (r < 16) {
        out[(c*Bb + b0 + g)*16 + r] = outv[g*16 + r];
    }
}

extern "C" void kernel_launch(void* const* d_in, const int* in_sizes, int n_in,
                              void* d_out, int out_size)
{
    const float* x = (const float*)d_in[0];
    const float* w = (const float*)d_in[1];
    float* out = (float*)d_out;

    cudaFuncSetAttribute(capsule_routing_kernel,
                         cudaFuncAttributeMaxDynamicSharedMemorySize, SMEM_BYTES);

    const int grid = Cc * (Bb / Gg);   // 1280 CTAs
    capsule_routing_kernel<<<grid, NTHREADS, SMEM_BYTES>>>(x, w, out);
}